// round 1
// baseline (speedup 1.0000x reference)
#include <cuda_runtime.h>

// Problem constants
#define TT   1024   // seq len
#define BB   1024   // batch
#define HH   64     // encoder hidden
#define NG   256    // 4*H gate rows
#define NB   7      // batch elements per encoder CTA
#define ENC_CTAS 147  // ceil(1024/7)

// Scratch for encoder final hidden state (device global: no allocation allowed)
__device__ float g_henc[BB * HH];

// ---------------------------------------------------------------------------
// helpers
// ---------------------------------------------------------------------------
__device__ __forceinline__ void ffma2(unsigned long long &d,
                                      unsigned long long a,
                                      unsigned long long b) {
    // packed f32x2 FMA: d = a*b + d (two MACs per lane-op)
    asm("fma.rn.f32x2 %0, %1, %2, %0;" : "+l"(d) : "l"(a), "l"(b));
}
__device__ __forceinline__ float ex2f(float x) {
    float r; asm("ex2.approx.f32 %0, %1;" : "=f"(r) : "f"(x)); return r;
}
__device__ __forceinline__ float rcpf(float x) {
    float r; asm("rcp.approx.f32 %0, %1;" : "=f"(r) : "f"(x)); return r;
}

#define L2E  1.4426950408889634f
#define TWO_L2E 2.8853900817779268f

// ---------------------------------------------------------------------------
// Encoder: one CTA = NB batch elements for the full T loop.
// 256 threads; thread r owns gate row r (weights in registers, k-packed f32x2).
// Gate order (PyTorch/JAX i,f,g,o): rows 0-63 i, 64-127 f, 128-191 g, 192-255 o.
// The sigmoid/tanh argument scale (-log2e or 2*log2e) is folded into the
// weights/bias/x-coef at load, so activation = fma(A, rcp(1+ex2(g')), B).
// ---------------------------------------------------------------------------
__global__ void __launch_bounds__(256, 1) enc_kernel(
    const float* __restrict__ x,      // [T, B, 1]
    const float* __restrict__ Wih,    // [256, 1]
    const float* __restrict__ Whh,    // [256, 64]
    const float* __restrict__ bih,    // [256]
    const float* __restrict__ bhh)    // [256]
{
    const int r  = threadIdx.x;
    const int b0 = blockIdx.x * NB;

    __shared__ __align__(16) float hs[NB][HH];   // hidden state (packed-pair reads)
    __shared__ float gs[NB][NG];                 // activated gate values
    __shared__ float xs[2][NB];                  // double-buffered x broadcast

    // per-row activation parametrization
    const bool isTanh = (r >= 128) && (r < 192);
    const float s  = isTanh ? TWO_L2E : -L2E;    // fold into pre-activation
    const float A  = isTanh ? -2.0f : 1.0f;      // act = A*rcp(1+ex2(g')) + Bc
    const float Bc = isTanh ?  1.0f : 0.0f;

    // load this thread's gate row of Whh, pre-scaled, as 32 packed f32x2 regs
    unsigned long long w2[32];
    {
        const float2* wp = (const float2*)(Whh + r * HH);
        #pragma unroll
        for (int i = 0; i < 32; i++) {
            float2 v = wp[i];
            float vx = v.x * s, vy = v.y * s;
            asm("mov.b64 %0, {%1,%2};" : "=l"(w2[i]) : "f"(vx), "f"(vy));
        }
    }
    const float be   = s * (bih[r] + bhh[r]);
    const float wihr = s * Wih[r];     // IN==1: rank-1 input term

    // init h = 0 and stage x for t=0
    for (int i = r; i < NB * HH; i += 256) ((float*)hs)[i] = 0.0f;
    if (r < NB) {
        int gb = b0 + r; if (gb > BB - 1) gb = BB - 1;
        xs[0][r] = x[gb];             // x[0*B + gb]
    }
    float c0 = 0.0f, c1 = 0.0f;       // cell state lives in registers
    __syncthreads();

    for (int t = 0; t < TT; t++) {
        // prefetch next step's x early (LDG latency hidden under the matvec)
        float xv = 0.0f;
        if ((r < NB) && (t + 1 < TT)) {
            int gb = b0 + r; if (gb > BB - 1) gb = BB - 1;
            xv = __ldg(&x[(t + 1) * BB + gb]);
        }

        // ---- matvec: gates(r, b) = sum_k Whh'[r][k] * h[b][k] ----
        unsigned long long acc[NB];
        #pragma unroll
        for (int b = 0; b < NB; b++) acc[b] = 0ull;   // packed (0.f, 0.f)

        #pragma unroll
        for (int kk = 0; kk < 16; kk++) {
            #pragma unroll
            for (int b = 0; b < NB; b++) {
                // broadcast LDS.128: 4 consecutive h values (2 packed pairs)
                ulonglong2 h4 = ((const ulonglong2*)hs[b])[kk];
                ffma2(acc[b], w2[2 * kk],     h4.x);
                ffma2(acc[b], w2[2 * kk + 1], h4.y);
            }
        }

        // ---- finalize + activation ----
        #pragma unroll
        for (int b = 0; b < NB; b++) {
            float lo, hi;
            asm("mov.b64 {%0,%1}, %2;" : "=f"(lo), "=f"(hi) : "l"(acc[b]));
            float g = lo + hi + be + wihr * xs[t & 1][b];
            gs[b][r] = fmaf(A, rcpf(1.0f + ex2f(g)), Bc);
        }
        if ((r < NB) && (t + 1 < TT)) xs[(t + 1) & 1][r] = xv;
        __syncthreads();

        // ---- c/h update: items u = b*64 + j, u in [0, NB*64) = [0,448) ----
        {
            int u = r;                       // first item (all 256 threads)
            {
                int b = u >> 6, j = u & 63;
                float ai = gs[b][j], af = gs[b][64 + j];
                float ag = gs[b][128 + j], ao = gs[b][192 + j];
                c0 = fmaf(af, c0, ai * ag);
                float tc = fmaf(-2.0f, rcpf(1.0f + ex2f(TWO_L2E * c0)), 1.0f);
                hs[b][j] = ao * tc;
            }
            u = r + 256;                     // second item (threads 0..191)
            if (u < NB * HH) {
                int b = u >> 6, j = u & 63;
                float ai = gs[b][j], af = gs[b][64 + j];
                float ag = gs[b][128 + j], ao = gs[b][192 + j];
                c1 = fmaf(af, c1, ai * ag);
                float tc = fmaf(-2.0f, rcpf(1.0f + ex2f(TWO_L2E * c1)), 1.0f);
                hs[b][j] = ao * tc;
            }
        }
        __syncthreads();
    }

    // write final hidden state (guard duplicated clamped batches)
    for (int i = r; i < NB * HH; i += 256) {
        int b = i >> 6, j = i & 63;
        int gb = b0 + b;
        if (gb < BB) g_henc[gb * HH + j] = hs[b][j];
    }
}

// ---------------------------------------------------------------------------
// Decoder: hidden size 1. Feed constant h_enc each step.
// z[b][g] = h_enc[b] @ Wih_d[g]^T + bd[g] is time-invariant -> precompute.
// Per step: 4 FMAs + 5 activations, pure scalar recurrence per batch element.
// ---------------------------------------------------------------------------
__global__ void __launch_bounds__(64) dec_kernel(
    const float* __restrict__ Wih_d,  // [4, 64]
    const float* __restrict__ Whh_d,  // [4, 1]
    const float* __restrict__ bih_d,  // [4]
    const float* __restrict__ bhh_d,  // [4]
    float* __restrict__ out)          // [T, B, 1]
{
    const int b = blockIdx.x * 64 + threadIdx.x;

    float z[4], w[4];
    #pragma unroll
    for (int g = 0; g < 4; g++) {
        float acc = bih_d[g] + bhh_d[g];
        const float* wr = Wih_d + g * HH;
        const float* he = g_henc + b * HH;
        #pragma unroll 8
        for (int k = 0; k < HH; k++) acc = fmaf(wr[k], he[k], acc);
        const float s = (g == 2) ? TWO_L2E : -L2E;   // tanh gate vs sigmoid gates
        z[g] = s * acc;
        w[g] = s * Whh_d[g];
    }

    float h = 0.0f, c = 0.0f;
    for (int t = 0; t < TT; t++) {
        float gi = fmaf(w[0], h, z[0]);
        float gf = fmaf(w[1], h, z[1]);
        float gg = fmaf(w[2], h, z[2]);
        float go = fmaf(w[3], h, z[3]);
        float ai = rcpf(1.0f + ex2f(gi));
        float af = rcpf(1.0f + ex2f(gf));
        float ag = fmaf(-2.0f, rcpf(1.0f + ex2f(gg)), 1.0f);
        float ao = rcpf(1.0f + ex2f(go));
        c = fmaf(af, c, ai * ag);
        float tc = fmaf(-2.0f, rcpf(1.0f + ex2f(TWO_L2E * c)), 1.0f);
        h = ao * tc;
        out[t * BB + b] = h;
    }
}

// ---------------------------------------------------------------------------
// launch
// ---------------------------------------------------------------------------
extern "C" void kernel_launch(void* const* d_in, const int* in_sizes, int n_in,
                              void* d_out, int out_size) {
    const float* x     = (const float*)d_in[0];
    const float* Wih_e = (const float*)d_in[1];
    const float* Whh_e = (const float*)d_in[2];
    const float* bih_e = (const float*)d_in[3];
    const float* bhh_e = (const float*)d_in[4];
    const float* Wih_d = (const float*)d_in[5];
    const float* Whh_d = (const float*)d_in[6];
    const float* bih_d = (const float*)d_in[7];
    const float* bhh_d = (const float*)d_in[8];
    float* out = (float*)d_out;

    enc_kernel<<<ENC_CTAS, 256>>>(x, Wih_e, Whh_e, bih_e, bhh_e);
    dec_kernel<<<BB / 64, 64>>>(Wih_d, Whh_d, bih_d, bhh_d, out);
}

// round 2
// speedup vs baseline: 1.0251x; 1.0251x over previous
#include <cuda_runtime.h>

// Problem constants
#define TT   1024   // seq len
#define BB   1024   // batch
#define HH   64     // encoder hidden
#define NB   7      // batch elements per encoder CTA
#define ENC_CTAS 147  // 147*7 = 1029 >= 1024

// Scratch for encoder final hidden state (device global: no allocation allowed)
__device__ float g_henc[BB * HH];

// ---------------------------------------------------------------------------
// helpers
// ---------------------------------------------------------------------------
__device__ __forceinline__ void ffma2(unsigned long long &d,
                                      unsigned long long a,
                                      unsigned long long b) {
    // packed f32x2 FMA: d = a*b + d (two MACs per op)
    asm("fma.rn.f32x2 %0, %1, %2, %0;" : "+l"(d) : "l"(a), "l"(b));
}
__device__ __forceinline__ float ex2f(float x) {
    float r; asm("ex2.approx.f32 %0, %1;" : "=f"(r) : "f"(x)); return r;
}
__device__ __forceinline__ float rcpf(float x) {
    float r; asm("rcp.approx.f32 %0, %1;" : "=f"(r) : "f"(x)); return r;
}

#define L2E      1.4426950408889634f
#define TWO_L2E  2.8853900817779268f

// exact-ish tanh via ex2+rcp (rel err ~1e-7): tanh(x) = 1 - 2/(1+e^{2x})
__device__ __forceinline__ float tanhx(float x) {
    return fmaf(-2.0f, rcpf(1.0f + ex2f(TWO_L2E * x)), 1.0f);
}

// ---------------------------------------------------------------------------
// Encoder, v2.
//   147 CTAs x 512 threads. CTA owns NB=7 batch chains for all 1024 steps.
//   Thread layout: sub = tid>>8 (2 subgroups: batches 0-3 / 4-6, weights
//   replicated); within subgroup, quad (j = (tid&255)>>2, g = tid&3) owns
//   gate row g*64+j, weights in registers (32 packed f32x2 pairs).
//   Per step per batch: 16x(LDS.128 broadcast h4 + 2 FFMA2) matvec,
//   activation (ex2+rcp), 4x shfl.idx quad gather, redundant c/h update.
//   hs double-buffered -> ONE __syncthreads per step.
//   Gate order i,f,g,o: g==2 is the tanh gate; activation arg scale folded
//   into weights/bias so act = fma(A, rcp(1+ex2(g')), B).
// ---------------------------------------------------------------------------
__global__ void __launch_bounds__(512, 1) enc_kernel(
    const float* __restrict__ x,      // [T, B, 1]
    const float* __restrict__ Wih,    // [256, 1]
    const float* __restrict__ Whh,    // [256, 64]
    const float* __restrict__ bih,    // [256]
    const float* __restrict__ bhh)    // [256]
{
    const int tid = threadIdx.x;
    const int sub = tid >> 8;                 // 0 or 1
    const int j   = (tid & 255) >> 2;         // 0..63
    const int g   = tid & 3;                  // gate index (i,f,g,o)
    const int row = g * HH + j;               // gate row 0..255
    const int b0  = blockIdx.x * NB;

    const int nb     = (sub == 0) ? 4 : 3;    // batches per subgroup
    const int b_base = sub * 4;

    __shared__ __align__(16) float hs[2][NB][HH];  // double-buffered hidden
    __shared__ float xs[2][8];                     // double-buffered x bcast

    // activation parametrization for this row (g==2 -> tanh)
    const bool isTanh = (g == 2);
    const float s  = isTanh ? TWO_L2E : -L2E;
    const float A  = isTanh ? -2.0f : 1.0f;
    const float Bc = isTanh ?  1.0f : 0.0f;

    // weights for my gate row, pre-scaled, as 32 packed f32x2 regs
    unsigned long long w2[32];
    {
        const float2* wp = (const float2*)(Whh + row * HH);
        #pragma unroll
        for (int i = 0; i < 32; i++) {
            float2 v = wp[i];
            float vx = v.x * s, vy = v.y * s;
            asm("mov.b64 %0, {%1,%2};" : "=l"(w2[i]) : "f"(vx), "f"(vy));
        }
    }
    const float be   = s * (bih[row] + bhh[row]);
    const float wihr = s * Wih[row];               // IN==1 rank-1 input term

    // init h=0 (buffer 0) and stage x for t=0
    for (int i = tid; i < NB * HH; i += 512) ((float*)hs[0])[i] = 0.0f;
    if (tid < NB) {
        int gb = b0 + tid; if (gb > BB - 1) gb = BB - 1;
        xs[0][tid] = x[gb];
    }
    float cc[4] = {0.0f, 0.0f, 0.0f, 0.0f};       // cell state (per batch)
    const int lb = (tid & 31) & ~3;               // quad base lane
    __syncthreads();

    for (int t = 0; t < TT; t++) {
        const float* __restrict__ hr = hs[t & 1][0];        // read buffer
        float* __restrict__       hw = hs[(t + 1) & 1][0];  // write buffer

        // prefetch next x (LDG latency hidden under the matvec)
        float xv = 0.0f;
        if ((tid < NB) && (t + 1 < TT)) {
            int gb = b0 + tid; if (gb > BB - 1) gb = BB - 1;
            xv = __ldg(&x[(t + 1) * BB + gb]);
        }

        for (int bi = 0; bi < nb; ++bi) {
            const int b = b_base + bi;
            const float* hb = hr + b * HH;

            // ---- matvec: gate(row, b) = sum_k Whh'[row][k] * h[b][k] ----
            unsigned long long acc = 0ull;
            #pragma unroll
            for (int kk = 0; kk < 16; kk++) {
                ulonglong2 h4 = ((const ulonglong2*)hb)[kk];  // LDS.128 bcast
                ffma2(acc, w2[2 * kk],     h4.x);
                ffma2(acc, w2[2 * kk + 1], h4.y);
            }
            float lo, hi;
            asm("mov.b64 {%0,%1}, %2;" : "=f"(lo), "=f"(hi) : "l"(acc));
            float gp  = lo + hi + be + wihr * xs[t & 1][b];
            float act = fmaf(A, rcpf(1.0f + ex2f(gp)), Bc);

            // ---- quad gather: (i,f,g,o) for (b, j) via shfl.idx ----
            float ai = __shfl_sync(0xffffffffu, act, lb + 0);
            float af = __shfl_sync(0xffffffffu, act, lb + 1);
            float ag = __shfl_sync(0xffffffffu, act, lb + 2);
            float ao = __shfl_sync(0xffffffffu, act, lb + 3);

            // ---- c/h update (redundant across the 4 quad lanes) ----
            cc[bi] = fmaf(af, cc[bi], ai * ag);
            float hnew = ao * tanhx(cc[bi]);
            if (g == 0) hw[b * HH + j] = hnew;
        }

        if ((tid < NB) && (t + 1 < TT)) xs[(t + 1) & 1][tid] = xv;
        __syncthreads();
    }

    // final hidden state lives in buffer 0 (t=1023 wrote (1024)&1 = 0)
    for (int i = tid; i < NB * HH; i += 512) {
        int b = i >> 6, jj = i & 63;
        int gb = b0 + b;
        if (gb < BB) g_henc[gb * HH + jj] = hs[0][b][jj];
    }
}

// ---------------------------------------------------------------------------
// Decoder: hidden size 1. z[b] = h_enc[b] @ Wih_d^T + bd is time-invariant;
// per step: 4 FMAs + 5 exact activations. Pure latency chain per batch.
// ---------------------------------------------------------------------------
__global__ void __launch_bounds__(64) dec_kernel(
    const float* __restrict__ Wih_d,  // [4, 64]
    const float* __restrict__ Whh_d,  // [4, 1]
    const float* __restrict__ bih_d,  // [4]
    const float* __restrict__ bhh_d,  // [4]
    float* __restrict__ out)          // [T, B, 1]
{
    const int b = blockIdx.x * 64 + threadIdx.x;

    float z[4], w[4];
    #pragma unroll
    for (int g = 0; g < 4; g++) {
        float acc = bih_d[g] + bhh_d[g];
        const float* wr = Wih_d + g * HH;
        const float* he = g_henc + b * HH;
        #pragma unroll 8
        for (int k = 0; k < HH; k++) acc = fmaf(wr[k], he[k], acc);
        const float s = (g == 2) ? TWO_L2E : -L2E;  // tanh gate vs sigmoids
        z[g] = s * acc;
        w[g] = s * Whh_d[g];
    }

    float h = 0.0f, c = 0.0f;
    float* op = out + b;
    for (int t = 0; t < TT; t++) {
        float gi = fmaf(w[0], h, z[0]);
        float gf = fmaf(w[1], h, z[1]);
        float gg = fmaf(w[2], h, z[2]);
        float go = fmaf(w[3], h, z[3]);
        float ai = rcpf(1.0f + ex2f(gi));
        float af = rcpf(1.0f + ex2f(gf));
        float ag = fmaf(-2.0f, rcpf(1.0f + ex2f(gg)), 1.0f);
        float ao = rcpf(1.0f + ex2f(go));
        c = fmaf(af, c, ai * ag);
        h = ao * tanhx(c);
        *op = h;
        op += BB;
    }
}

// ---------------------------------------------------------------------------
// launch
// ---------------------------------------------------------------------------
extern "C" void kernel_launch(void* const* d_in, const int* in_sizes, int n_in,
                              void* d_out, int out_size) {
    const float* x     = (const float*)d_in[0];
    const float* Wih_e = (const float*)d_in[1];
    const float* Whh_e = (const float*)d_in[2];
    const float* bih_e = (const float*)d_in[3];
    const float* bhh_e = (const float*)d_in[4];
    const float* Wih_d = (const float*)d_in[5];
    const float* Whh_d = (const float*)d_in[6];
    const float* bih_d = (const float*)d_in[7];
    const float* bhh_d = (const float*)d_in[8];
    float* out = (float*)d_out;

    enc_kernel<<<ENC_CTAS, 512>>>(x, Wih_e, Whh_e, bih_e, bhh_e);
    dec_kernel<<<BB / 64, 64>>>(Wih_d, Whh_d, bih_d, bhh_d, out);
}

// round 3
// speedup vs baseline: 1.2422x; 1.2117x over previous
#include <cuda_runtime.h>

// Problem constants
#define TT   1024   // seq len
#define BB   1024   // batch
#define HH   64     // encoder hidden
#define NB   7      // batch elements per CTA
#define ENC_CTAS 147  // 147*7 = 1029 >= 1024

// ---------------------------------------------------------------------------
// helpers
// ---------------------------------------------------------------------------
__device__ __forceinline__ void ffma2(unsigned long long &d,
                                      unsigned long long a,
                                      unsigned long long b) {
    // packed f32x2 FMA: d = a*b + d (two MACs per op)
    asm("fma.rn.f32x2 %0, %1, %2, %0;" : "+l"(d) : "l"(a), "l"(b));
}
__device__ __forceinline__ unsigned long long packf2(float lo, float hi) {
    unsigned long long r;
    asm("mov.b64 %0, {%1,%2};" : "=l"(r) : "f"(lo), "f"(hi));
    return r;
}
__device__ __forceinline__ float ex2f(float x) {
    float r; asm("ex2.approx.f32 %0, %1;" : "=f"(r) : "f"(x)); return r;
}
__device__ __forceinline__ float rcpf(float x) {
    float r; asm("rcp.approx.f32 %0, %1;" : "=f"(r) : "f"(x)); return r;
}

#define L2E      1.4426950408889634f
#define TWO_L2E  2.8853900817779268f

// exact-ish tanh via ex2+rcp (rel err ~1e-7): tanh(x) = 1 - 2/(1+e^{2x})
__device__ __forceinline__ float tanhx(float x) {
    return fmaf(-2.0f, rcpf(1.0f + ex2f(TWO_L2E * x)), 1.0f);
}

// ---------------------------------------------------------------------------
// Fused encoder+decoder. 147 CTAs x 384 threads; CTA owns NB=7 batch chains.
//
// Encoder thread layout:
//   sub  = tid>>7           (3 subgroups; batches {0,1,2} / {3,4} / {5,6})
//   j    = (tid&127)>>1     (0..63: hidden index)
//   half = tid&1            (0: gate rows (i,f) = (j, 64+j);
//                            1: gate rows (g,o) = (128+j, 192+j))
// Each thread holds 2 gate rows of Whh in registers as 64 packed f32x2 pairs
// -> per h LDS.128 (4 h values) we issue 4 FFMA2 (1:4 LDS:FMA ratio, halving
// SM-wide crossbar traffic vs the 1-row layout). Activation scale folded into
// weights/bias. Epilogue: butterfly shfl (lane^1) swaps (i,f)<->(g,o); both
// halves redundantly update c; half==0 stores h. hs double-buffered -> one
// __syncthreads per step.
//
// Decoder (hidden=1) fused at the end: z = h_enc @ Wih_d^T + bd is
// time-invariant; 7 threads run the 1024-step scalar recurrence from SMEM.
// ---------------------------------------------------------------------------
__global__ void __launch_bounds__(384, 1) fused_kernel(
    const float* __restrict__ x,      // [T, B, 1]
    const float* __restrict__ Wih,    // [256, 1]
    const float* __restrict__ Whh,    // [256, 64]
    const float* __restrict__ bih,    // [256]
    const float* __restrict__ bhh,    // [256]
    const float* __restrict__ Wih_d,  // [4, 64]
    const float* __restrict__ Whh_d,  // [4, 1]
    const float* __restrict__ bih_d,  // [4]
    const float* __restrict__ bhh_d,  // [4]
    float* __restrict__ out)          // [T, B, 1]
{
    const int tid  = threadIdx.x;
    const int sub  = tid >> 7;            // 0,1,2
    const int j    = (tid & 127) >> 1;    // 0..63
    const int half = tid & 1;             // 0 or 1
    const int r0   = half * 128 + j;      // i-gate (half0) / g-gate (half1)
    const int r1   = r0 + 64;             // f-gate (half0) / o-gate (half1)
    const int b0   = blockIdx.x * NB;

    const int nb     = (sub == 0) ? 3 : 2;
    const int b_base = (sub == 0) ? 0 : ((sub == 1) ? 3 : 5);

    __shared__ __align__(16) float hs[2][NB][HH];  // double-buffered hidden
    __shared__ float xs[2][8];                     // double-buffered x bcast

    // activation parametrization:
    //   r0: half0 = i (sigmoid), half1 = g (tanh)
    //   r1: f / o, both sigmoid
    const float s0 = half ? TWO_L2E : -L2E;
    const float s1 = -L2E;
    const float A0 = half ? -2.0f : 1.0f;
    const float B0 = half ?  1.0f : 0.0f;

    // weights for my two gate rows, pre-scaled, packed over k
    unsigned long long w0[32], w1[32];
    {
        const float2* p0 = (const float2*)(Whh + r0 * HH);
        const float2* p1 = (const float2*)(Whh + r1 * HH);
        #pragma unroll
        for (int i = 0; i < 32; i++) {
            float2 v0 = p0[i], v1 = p1[i];
            w0[i] = packf2(v0.x * s0, v0.y * s0);
            w1[i] = packf2(v1.x * s1, v1.y * s1);
        }
    }
    const float be0  = s0 * (bih[r0] + bhh[r0]);
    const float be1  = s1 * (bih[r1] + bhh[r1]);
    const float wih0 = s0 * Wih[r0];
    const float wih1 = s1 * Wih[r1];

    // init h=0 (buffer 0), stage x for t=0
    for (int i = tid; i < NB * HH; i += 384) ((float*)hs[0])[i] = 0.0f;
    if (tid < NB) {
        int gb = b0 + tid; if (gb > BB - 1) gb = BB - 1;
        xs[0][tid] = x[gb];
    }
    float cc[3] = {0.0f, 0.0f, 0.0f};
    __syncthreads();

    for (int t = 0; t < TT; t++) {
        const float* __restrict__ hr = hs[t & 1][0];
        float* __restrict__       hw = hs[(t + 1) & 1][0];

        // prefetch next x (LDG latency hidden under the matvec)
        float xv = 0.0f;
        if ((tid < NB) && (t + 1 < TT)) {
            int gb = b0 + tid; if (gb > BB - 1) gb = BB - 1;
            xv = __ldg(&x[(t + 1) * BB + gb]);
        }

        #pragma unroll
        for (int bi = 0; bi < 3; ++bi) {
            if (bi < nb) {                       // warp-uniform predicate
                const int b = b_base + bi;
                const float* hb = hr + b * HH;
                const float xb = xs[t & 1][b];

                // bias + input-term folded into packed accumulator init
                unsigned long long a0 = packf2(fmaf(wih0, xb, be0), 0.0f);
                unsigned long long a1 = packf2(fmaf(wih1, xb, be1), 0.0f);

                #pragma unroll
                for (int kk = 0; kk < 16; kk++) {
                    ulonglong2 h4 = ((const ulonglong2*)hb)[kk]; // LDS.128 bcast
                    ffma2(a0, w0[2 * kk],     h4.x);
                    ffma2(a0, w0[2 * kk + 1], h4.y);
                    ffma2(a1, w1[2 * kk],     h4.x);
                    ffma2(a1, w1[2 * kk + 1], h4.y);
                }
                float l0, h0, l1, h1;
                asm("mov.b64 {%0,%1}, %2;" : "=f"(l0), "=f"(h0) : "l"(a0));
                asm("mov.b64 {%0,%1}, %2;" : "=f"(l1), "=f"(h1) : "l"(a1));
                float act0 = fmaf(A0, rcpf(1.0f + ex2f(l0 + h0)), B0);
                float act1 = rcpf(1.0f + ex2f(l1 + h1));

                // butterfly exchange with partner lane (other gate pair)
                float p0v = __shfl_xor_sync(0xffffffffu, act0, 1);
                float p1v = __shfl_xor_sync(0xffffffffu, act1, 1);
                float ai = half ? p0v  : act0;
                float af = half ? p1v  : act1;
                float ag = half ? act0 : p0v;
                float ao = half ? act1 : p1v;

                cc[bi] = fmaf(af, cc[bi], ai * ag);
                float hn = ao * tanhx(cc[bi]);
                if (!half) hw[b * HH + j] = hn;
            }
        }

        if ((tid < NB) && (t + 1 < TT)) xs[(t + 1) & 1][tid] = xv;
        __syncthreads();
    }
    // final hidden state is in hs[0] (t=1023 wrote buffer (1024)&1 = 0)

    // ------------------- fused decoder (7 threads per CTA) -------------------
    if (tid < NB) {
        const int gb = b0 + tid;
        if (gb < BB) {
            const float* he = hs[0][tid];
            float z[4], w[4];
            #pragma unroll
            for (int g = 0; g < 4; g++) {
                float acc = bih_d[g] + bhh_d[g];
                const float* wr = Wih_d + g * HH;
                #pragma unroll 8
                for (int k = 0; k < HH; k++) acc = fmaf(wr[k], he[k], acc);
                const float s = (g == 2) ? TWO_L2E : -L2E;
                z[g] = s * acc;
                w[g] = s * Whh_d[g];
            }
            float h = 0.0f, c = 0.0f;
            float* op = out + gb;
            for (int t = 0; t < TT; t++) {
                float gi = fmaf(w[0], h, z[0]);
                float gf = fmaf(w[1], h, z[1]);
                float gg = fmaf(w[2], h, z[2]);
                float go = fmaf(w[3], h, z[3]);
                float ai = rcpf(1.0f + ex2f(gi));
                float af = rcpf(1.0f + ex2f(gf));
                float ag = fmaf(-2.0f, rcpf(1.0f + ex2f(gg)), 1.0f);
                float ao = rcpf(1.0f + ex2f(go));
                c = fmaf(af, c, ai * ag);
                h = ao * tanhx(c);
                *op = h;
                op += BB;
            }
        }
    }
}

// ---------------------------------------------------------------------------
// launch
// ---------------------------------------------------------------------------
extern "C" void kernel_launch(void* const* d_in, const int* in_sizes, int n_in,
                              void* d_out, int out_size) {
    const float* x     = (const float*)d_in[0];
    const float* Wih_e = (const float*)d_in[1];
    const float* Whh_e = (const float*)d_in[2];
    const float* bih_e = (const float*)d_in[3];
    const float* bhh_e = (const float*)d_in[4];
    const float* Wih_d = (const float*)d_in[5];
    const float* Whh_d = (const float*)d_in[6];
    const float* bih_d = (const float*)d_in[7];
    const float* bhh_d = (const float*)d_in[8];
    float* out = (float*)d_out;

    fused_kernel<<<ENC_CTAS, 384>>>(x, Wih_e, Whh_e, bih_e, bhh_e,
                                    Wih_d, Whh_d, bih_d, bhh_d, out);
}

// round 4
// speedup vs baseline: 1.4054x; 1.1314x over previous
#include <cuda_runtime.h>

// Problem constants
#define TT   1024   // seq len
#define BB   1024   // batch
#define HH   64     // encoder hidden
#define NB   7      // batch elements per CTA
#define CTAS 147    // 147*7 = 1029 >= 1024

// ---------------------------------------------------------------------------
// helpers
// ---------------------------------------------------------------------------
__device__ __forceinline__ void ffma2(unsigned long long &d,
                                      unsigned long long a,
                                      unsigned long long b) {
    // packed f32x2 FMA: d = a*b + d (two MACs per op)
    asm("fma.rn.f32x2 %0, %1, %2, %0;" : "+l"(d) : "l"(a), "l"(b));
}
__device__ __forceinline__ unsigned long long packf2(float lo, float hi) {
    unsigned long long r;
    asm("mov.b64 %0, {%1,%2};" : "=l"(r) : "f"(lo), "f"(hi));
    return r;
}
__device__ __forceinline__ float ex2f(float x) {
    float r; asm("ex2.approx.f32 %0, %1;" : "=f"(r) : "f"(x)); return r;
}
__device__ __forceinline__ float rcpf(float x) {
    float r; asm("rcp.approx.f32 %0, %1;" : "=f"(r) : "f"(x)); return r;
}

#define L2E      1.4426950408889634f
#define TWO_L2E  2.8853900817779268f

// exact-ish tanh via ex2+rcp (rel err ~1e-7): tanh(x) = 1 - 2/(1+e^{2x})
__device__ __forceinline__ float tanhx(float x) {
    return fmaf(-2.0f, rcpf(1.0f + ex2f(TWO_L2E * x)), 1.0f);
}

// ---------------------------------------------------------------------------
// Fused encoder+decoder. 147 CTAs x 256 threads; CTA owns NB=7 batch chains.
//
// Thread layout:
//   sub  = tid>>7        (2 subgroups; batches {0..3} / {4..6})
//   j    = (tid&127)>>1  (hidden index 0..63)
//   half = tid&1         (0: gate rows (i,f) = (j, j+64);
//                         1: gate rows (g,o) = (j+128, j+192))
// 2 gate rows of Whh per thread in regs (64 packed f32x2). The ONLY cross-
// thread state is hs, which is subgroup-private -> per-subgroup named
// barriers (bar.sync sub+1, 128) instead of __syncthreads, letting the two
// subgroups drift and interleave their matvec/epilogue phases on each SMSP.
// x is loaded per-thread via warp-uniform __ldg, prefetched one step ahead.
// Explicit phase split: all nb matvecs into live packed accumulators, then
// all epilogues (independent MUFU chains). One barrier per step.
// Epilogue: butterfly shfl (lane^1) exchanges (i,f)<->(g,o); both halves
// redundantly hold c; half==0 stores h.
//
// Decoder (hidden=1) fused at the end after a full __syncthreads.
// ---------------------------------------------------------------------------
__global__ void __launch_bounds__(256, 1) fused_kernel(
    const float* __restrict__ x,      // [T, B, 1]
    const float* __restrict__ Wih,    // [256, 1]
    const float* __restrict__ Whh,    // [256, 64]
    const float* __restrict__ bih,    // [256]
    const float* __restrict__ bhh,    // [256]
    const float* __restrict__ Wih_d,  // [4, 64]
    const float* __restrict__ Whh_d,  // [4, 1]
    const float* __restrict__ bih_d,  // [4]
    const float* __restrict__ bhh_d,  // [4]
    float* __restrict__ out)          // [T, B, 1]
{
    const int tid  = threadIdx.x;
    const int sub  = tid >> 7;            // 0 or 1
    const int j    = (tid & 127) >> 1;    // 0..63
    const int half = tid & 1;
    const int r0   = half * 128 + j;      // i (half0) / g (half1)
    const int r1   = r0 + 64;             // f (half0) / o (half1)
    const int b0   = blockIdx.x * NB;

    const int nb     = sub ? 3 : 4;
    const int b_base = sub ? 4 : 0;

    __shared__ __align__(16) float hs[2][NB][HH];  // double-buffered hidden

    // activation parametrization (r0: sigmoid/tanh, r1: sigmoid)
    const float s0 = half ? TWO_L2E : -L2E;
    const float s1 = -L2E;
    const float A0 = half ? -2.0f : 1.0f;
    const float B0 = half ?  1.0f : 0.0f;

    // weights for my two gate rows, pre-scaled, packed over k
    unsigned long long w0[32], w1[32];
    {
        const float2* p0 = (const float2*)(Whh + r0 * HH);
        const float2* p1 = (const float2*)(Whh + r1 * HH);
        #pragma unroll
        for (int i = 0; i < 32; i++) {
            float2 v0 = p0[i], v1 = p1[i];
            w0[i] = packf2(v0.x * s0, v0.y * s0);
            w1[i] = packf2(v1.x * s1, v1.y * s1);
        }
    }
    const float be0  = s0 * (bih[r0] + bhh[r0]);
    const float be1  = s1 * (bih[r1] + bhh[r1]);
    const float wih0 = s0 * Wih[r0];
    const float wih1 = s1 * Wih[r1];

    // per-batch x base pointers (clamped duplicate batches are deterministic)
    const float* xp[4];
    #pragma unroll
    for (int bi = 0; bi < 4; bi++) {
        int gb = b0 + b_base + bi; if (gb > BB - 1) gb = BB - 1;
        xp[bi] = x + gb;
    }
    float xv[4];
    #pragma unroll
    for (int bi = 0; bi < 4; bi++)
        if (bi < nb) xv[bi] = __ldg(xp[bi]);          // x at t=0

    // init h = 0 (buffer 0)
    for (int i = tid; i < NB * HH; i += 256) ((float*)hs[0])[i] = 0.0f;
    float cc[4] = {0.0f, 0.0f, 0.0f, 0.0f};
    __syncthreads();

    for (int t = 0; t < TT; t++) {
        const float* __restrict__ hr = hs[t & 1][0];
        float* __restrict__       hw = hs[(t + 1) & 1][0];

        // ---- accumulator init: bias + input term (uses this step's x) ----
        unsigned long long a0[4], a1[4];
        #pragma unroll
        for (int bi = 0; bi < 4; bi++) if (bi < nb) {
            a0[bi] = packf2(fmaf(wih0, xv[bi], be0), 0.0f);
            a1[bi] = packf2(fmaf(wih1, xv[bi], be1), 0.0f);
        }

        // ---- prefetch next step's x (latency hidden under the matvec) ----
        if (t + 1 < TT) {
            #pragma unroll
            for (int bi = 0; bi < 4; bi++)
                if (bi < nb) xv[bi] = __ldg(xp[bi] + (t + 1) * BB);
        }

        // ---- matvec phase: all batches, dense FFMA2 ----
        #pragma unroll
        for (int kk = 0; kk < 16; kk++) {
            #pragma unroll
            for (int bi = 0; bi < 4; bi++) if (bi < nb) {
                ulonglong2 h4 =
                    ((const ulonglong2*)(hr + (b_base + bi) * HH))[kk];
                ffma2(a0[bi], w0[2 * kk],     h4.x);
                ffma2(a0[bi], w0[2 * kk + 1], h4.y);
                ffma2(a1[bi], w1[2 * kk],     h4.x);
                ffma2(a1[bi], w1[2 * kk + 1], h4.y);
            }
        }

        // ---- epilogue phase: activations (independent MUFU chains) ----
        float act0[4], act1[4];
        #pragma unroll
        for (int bi = 0; bi < 4; bi++) if (bi < nb) {
            float l0, h0, l1, h1;
            asm("mov.b64 {%0,%1}, %2;" : "=f"(l0), "=f"(h0) : "l"(a0[bi]));
            asm("mov.b64 {%0,%1}, %2;" : "=f"(l1), "=f"(h1) : "l"(a1[bi]));
            act0[bi] = fmaf(A0, rcpf(1.0f + ex2f(l0 + h0)), B0);
            act1[bi] = rcpf(1.0f + ex2f(l1 + h1));
        }

        // ---- butterfly exchange with partner lane (other gate pair) ----
        float p0[4], p1[4];
        #pragma unroll
        for (int bi = 0; bi < 4; bi++) if (bi < nb) {
            p0[bi] = __shfl_xor_sync(0xffffffffu, act0[bi], 1);
            p1[bi] = __shfl_xor_sync(0xffffffffu, act1[bi], 1);
        }

        // ---- c/h update (c redundant across the lane pair) ----
        #pragma unroll
        for (int bi = 0; bi < 4; bi++) if (bi < nb) {
            float ai = half ? p0[bi]   : act0[bi];
            float af = half ? p1[bi]   : act1[bi];
            float ag = half ? act0[bi] : p0[bi];
            float ao = half ? act1[bi] : p1[bi];
            cc[bi] = fmaf(af, cc[bi], ai * ag);
            float hn = ao * tanhx(cc[bi]);
            if (!half) hw[(b_base + bi) * HH + j] = hn;
        }

        // per-subgroup barrier: hs is subgroup-private, so subgroups drift
        asm volatile("bar.sync %0, %1;" :: "r"(sub + 1), "r"(128) : "memory");
    }
    // final hidden state is in hs[0] (t=1023 wrote buffer (1024)&1 = 0)
    __syncthreads();   // decoder threads read other subgroup's batches

    // ------------------- fused decoder (7 threads per CTA) -------------------
    if (tid < NB) {
        const int gb = b0 + tid;
        if (gb < BB) {
            const float* he = hs[0][tid];
            float z[4], w[4];
            #pragma unroll
            for (int g = 0; g < 4; g++) {
                float acc = bih_d[g] + bhh_d[g];
                const float* wr = Wih_d + g * HH;
                #pragma unroll 8
                for (int k = 0; k < HH; k++) acc = fmaf(wr[k], he[k], acc);
                const float s = (g == 2) ? TWO_L2E : -L2E;
                z[g] = s * acc;
                w[g] = s * Whh_d[g];
            }
            float h = 0.0f, c = 0.0f;
            float* op = out + gb;
            for (int t = 0; t < TT; t++) {
                float gi = fmaf(w[0], h, z[0]);
                float gf = fmaf(w[1], h, z[1]);
                float gg = fmaf(w[2], h, z[2]);
                float go = fmaf(w[3], h, z[3]);
                float ai = rcpf(1.0f + ex2f(gi));
                float af = rcpf(1.0f + ex2f(gf));
                float ag = fmaf(-2.0f, rcpf(1.0f + ex2f(gg)), 1.0f);
                float ao = rcpf(1.0f + ex2f(go));
                c = fmaf(af, c, ai * ag);
                h = ao * tanhx(c);
                *op = h;
                op += BB;
            }
        }
    }
}

// ---------------------------------------------------------------------------
// launch
// ---------------------------------------------------------------------------
extern "C" void kernel_launch(void* const* d_in, const int* in_sizes, int n_in,
                              void* d_out, int out_size) {
    const float* x     = (const float*)d_in[0];
    const float* Wih_e = (const float*)d_in[1];
    const float* Whh_e = (const float*)d_in[2];
    const float* bih_e = (const float*)d_in[3];
    const float* bhh_e = (const float*)d_in[4];
    const float* Wih_d = (const float*)d_in[5];
    const float* Whh_d = (const float*)d_in[6];
    const float* bih_d = (const float*)d_in[7];
    const float* bhh_d = (const float*)d_in[8];
    float* out = (float*)d_out;

    fused_kernel<<<CTAS, 256>>>(x, Wih_e, Whh_e, bih_e, bhh_e,
                                Wih_d, Whh_d, bih_d, bhh_d, out);
}